// round 7
// baseline (speedup 1.0000x reference)
#include <cuda_runtime.h>
#include <cuda_bf16.h>
#include <cstdint>
#include <limits.h>

#define NPTS 4096
#define DIM  768
#define WD   64
#define KTOP 100

#define BM   128
#define NKT  (DIM / 16)     // 48 k-steps of 16
#define PADK 24             // smem row stride in bf16 elems (48B -> conflict-free LDSM)
#define TAU  1.5f           // |acc| below this -> exact fp32 sign repair

// scratch (no allocations allowed)
__device__ int            g_counts[NPTS];
__device__ int            g_seed;
__device__ float          g_simseed[NPTS];
__device__ int            g_s[NPTS];
__device__ __nv_bfloat16  g_Xb[NPTS * DIM];     // bf16 copy of X (6.3MB)

// ---------------------------------------------------------------------------
// helpers: ldmatrix + mma
// ---------------------------------------------------------------------------
__device__ __forceinline__ void ldsm_x4(uint32_t r[4], uint32_t addr) {
    asm volatile("ldmatrix.sync.aligned.m8n8.x4.shared.b16 {%0,%1,%2,%3}, [%4];"
                 : "=r"(r[0]), "=r"(r[1]), "=r"(r[2]), "=r"(r[3]) : "r"(addr));
}
__device__ __forceinline__ void mma_bf16(float d[4], const uint32_t a[4],
                                         uint32_t b0, uint32_t b1) {
    asm volatile("mma.sync.aligned.m16n8k16.row.col.f32.bf16.bf16.f32 "
                 "{%0,%1,%2,%3},{%4,%5,%6,%7},{%8,%9},{%0,%1,%2,%3};"
                 : "+f"(d[0]), "+f"(d[1]), "+f"(d[2]), "+f"(d[3])
                 : "r"(a[0]), "r"(a[1]), "r"(a[2]), "r"(a[3]), "r"(b0), "r"(b1));
}

__device__ __forceinline__ float exact_dot(const float* __restrict__ X, int gi, int gj) {
    const float4* a = (const float4*)(X + (size_t)gi * DIM);
    const float4* b = (const float4*)(X + (size_t)gj * DIM);
    float s = 0.0f;
    #pragma unroll 4
    for (int d = 0; d < DIM / 4; d++) {
        float4 u = a[d], w = b[d];
        s += u.x * w.x + u.y * w.y + u.z * w.z + u.w * w.w;
    }
    return s;
}

// ---------------------------------------------------------------------------
// 0a) fp32 -> bf16 conversion (one pass, ~5us)
// ---------------------------------------------------------------------------
__global__ void convert_bf16(const float* __restrict__ X) {
    int i = blockIdx.x * blockDim.x + threadIdx.x;   // one float4 per thread
    float4 v = ((const float4*)X)[i];
    __nv_bfloat162* o = (__nv_bfloat162*)g_Xb;
    o[2 * i + 0] = __floats2bfloat162_rn(v.x, v.y);
    o[2 * i + 1] = __floats2bfloat162_rn(v.z, v.w);
}

// ---------------------------------------------------------------------------
// 0b) init counts to 1 (diagonal sim[i][i] >= 0 always)
// ---------------------------------------------------------------------------
__global__ void init_counts() {
    int i = blockIdx.x * blockDim.x + threadIdx.x;
    if (i < NPTS) g_counts[i] = 1;
}

// ---------------------------------------------------------------------------
// 1) triangular count-GEMM on tensor cores (bf16 mma + exact fp32 sign repair)
//    128x128 tile, 8 warps (4x2), warp tile 32x64, m16n8k16.
// ---------------------------------------------------------------------------
__global__ __launch_bounds__(256, 2)
void count_mma(const float* __restrict__ X) {
    int bi = blockIdx.y, bj = blockIdx.x;
    if (bj < bi) return;

    __shared__ __nv_bfloat16 As[2][BM * PADK];
    __shared__ __nv_bfloat16 Bs[2][BM * PADK];
    __shared__ int rowSum[BM];
    __shared__ int colSum[BM];

    int tid  = threadIdx.x;
    int warp = tid >> 5, lane = tid & 31;
    int wm = warp & 3;          // M group: rows wm*32..+31
    int wn = warp >> 2;         // N group: cols wn*64..+63
    int i0 = bi * BM, j0 = bj * BM;

    float acc[2][8][4];
    #pragma unroll
    for (int im = 0; im < 2; im++)
        #pragma unroll
        for (int jn = 0; jn < 8; jn++)
            #pragma unroll
            for (int e = 0; e < 4; e++) acc[im][jn][e] = 0.0f;

    // global load mapping: thread -> (row, 16B half) of the 128x16 stage
    int lrow = tid >> 1, lhalf = tid & 1;
    const uint4* ga = (const uint4*)(g_Xb + (size_t)(i0 + lrow) * DIM);
    const uint4* gb = (const uint4*)(g_Xb + (size_t)(j0 + lrow) * DIM);
    uint4* sa = (uint4*)(&As[0][lrow * PADK + lhalf * 8]);
    uint4* sb = (uint4*)(&Bs[0][lrow * PADK + lhalf * 8]);
    const int bufU4 = (BM * PADK) / 8;   // uint4 stride between buffers

    // ldmatrix source lanes
    int rowA  = lane & 15;
    int koffA = (lane >> 4) * 8;
    int grp   = lane >> 3;
    int nB    = ((grp >> 1) * 8) + (lane & 7);
    int koffB = (grp & 1) * 8;

    uint32_t aAddr[2], bAddr[4];
    {
        uint32_t ab = (uint32_t)__cvta_generic_to_shared(&As[0][0]);
        uint32_t bb = (uint32_t)__cvta_generic_to_shared(&Bs[0][0]);
        #pragma unroll
        for (int im = 0; im < 2; im++)
            aAddr[im] = ab + ((wm * 32 + im * 16 + rowA) * PADK + koffA) * 2;
        #pragma unroll
        for (int jb = 0; jb < 4; jb++)
            bAddr[jb] = bb + ((wn * 64 + jb * 16 + nB) * PADK + koffB) * 2;
    }
    const uint32_t bufBytes = BM * PADK * 2;

    uint4 ra, rb;
    ra = ga[lhalf];  rb = gb[lhalf];
    sa[0] = ra;      sb[0] = rb;
    __syncthreads();

    for (int kt = 0; kt < NKT; kt++) {
        int buf = kt & 1;
        if (kt + 1 < NKT) {
            ra = ga[(kt + 1) * 2 + lhalf];
            rb = gb[(kt + 1) * 2 + lhalf];
        }

        uint32_t afr[2][4], bfr[4][4];
        #pragma unroll
        for (int im = 0; im < 2; im++) ldsm_x4(afr[im], aAddr[im] + buf * bufBytes);
        #pragma unroll
        for (int jb = 0; jb < 4; jb++) ldsm_x4(bfr[jb], bAddr[jb] + buf * bufBytes);

        #pragma unroll
        for (int im = 0; im < 2; im++)
            #pragma unroll
            for (int jn = 0; jn < 8; jn++)
                mma_bf16(acc[im][jn], afr[im],
                         bfr[jn >> 1][(jn & 1) * 2], bfr[jn >> 1][(jn & 1) * 2 + 1]);

        if (kt + 1 < NKT) {
            sa[(buf ^ 1) * bufU4] = ra;
            sb[(buf ^ 1) * bufU4] = rb;
        }
        __syncthreads();
    }

    // ---- epilogue: signs (+ exact repair), row/col counts ----
    if (tid < BM) { rowSum[tid] = 0; colSum[tid] = 0; }
    __syncthreads();

    bool diag = (bi == bj);
    int rcnt[2][2];  rcnt[0][0] = rcnt[0][1] = rcnt[1][0] = rcnt[1][1] = 0;
    int ccnt[16];
    #pragma unroll
    for (int q = 0; q < 16; q++) ccnt[q] = 0;

    int rbase = wm * 32 + (lane >> 2);
    int cbase = wn * 64 + (lane & 3) * 2;

    #pragma unroll
    for (int im = 0; im < 2; im++) {
        #pragma unroll
        for (int jn = 0; jn < 8; jn++) {
            #pragma unroll
            for (int e4 = 0; e4 < 4; e4++) {
                int h = e4 >> 1, e = e4 & 1;
                int gi = i0 + rbase + im * 16 + h * 8;
                int gj = j0 + cbase + jn * 8 + e;
                if (diag && gj <= gi) continue;
                float v = acc[im][jn][e4];
                int c;
                if (fabsf(v) >= TAU) c = (v >= 0.0f);
                else                 c = (exact_dot(X, gi, gj) >= 0.0f);
                rcnt[im][h] += c;
                ccnt[jn * 2 + e] += c;
            }
        }
    }
    #pragma unroll
    for (int im = 0; im < 2; im++)
        #pragma unroll
        for (int h = 0; h < 2; h++)
            atomicAdd(&rowSum[rbase + im * 16 + h * 8], rcnt[im][h]);
    #pragma unroll
    for (int jn = 0; jn < 8; jn++)
        #pragma unroll
        for (int e = 0; e < 2; e++)
            atomicAdd(&colSum[cbase + jn * 8 + e], ccnt[jn * 2 + e]);
    __syncthreads();

    if (tid < BM) {
        if (rowSum[tid]) atomicAdd(&g_counts[i0 + tid], rowSum[tid]);
        if (colSum[tid]) atomicAdd(&g_counts[j0 + tid], colSum[tid]);
    }
}

// ---------------------------------------------------------------------------
// 2) argmin of counts (first occurrence) + seed blend w/ round-half-to-even
// ---------------------------------------------------------------------------
__global__ void seed_kernel(const int* __restrict__ attn_seed) {
    __shared__ int bestC[256], bestI[256];
    int tid = threadIdx.x;
    int bc = INT_MAX, bi = 0;
    for (int i = tid; i < NPTS; i += 256) {
        int c = g_counts[i];
        if (c < bc) { bc = c; bi = i; }
    }
    bestC[tid] = bc; bestI[tid] = bi;
    __syncthreads();
    for (int s = 128; s > 0; s >>= 1) {
        if (tid < s) {
            if (bestC[tid + s] < bestC[tid] ||
                (bestC[tid + s] == bestC[tid] && bestI[tid + s] < bestI[tid])) {
                bestC[tid] = bestC[tid + s];
                bestI[tid] = bestI[tid + s];
            }
        }
        __syncthreads();
    }
    if (tid == 0) {
        int idx = bestI[0];
        int r = idx / WD, c = idx % WD;
        int tr = r + attn_seed[0];
        int tc = c + attn_seed[1];
        int rr = tr >> 1; if (tr & 1) rr += (rr & 1);   // round half-to-even
        int cc = tc >> 1; if (tc & 1) cc += (cc & 1);
        g_seed = rr * WD + cc;
    }
}

// ---------------------------------------------------------------------------
// 3) sim[seed][j] for all j + initial mask s[j] = (sim >= 0). warp per j.
// ---------------------------------------------------------------------------
__global__ void seedrow_kernel(const float* __restrict__ X) {
    int gwarp = (blockIdx.x * blockDim.x + threadIdx.x) >> 5;
    int lane  = threadIdx.x & 31;
    if (gwarp >= NPTS) return;
    int seed = g_seed;
    const float* xs = X + (size_t)seed * DIM;
    const float* xj = X + (size_t)gwarp * DIM;
    float p = 0.0f;
    for (int d = lane; d < DIM; d += 32) p += xs[d] * xj[d];
    #pragma unroll
    for (int o = 16; o > 0; o >>= 1) p += __shfl_down_sync(0xffffffffu, p, o);
    if (lane == 0) {
        g_simseed[gwarp] = p;
        g_s[gwarp] = (p >= 0.0f) ? 1 : 0;
    }
}

// ---------------------------------------------------------------------------
// 4) bitonic sort (desc value, asc index tiebreak) -> keep top-100, mask s
// ---------------------------------------------------------------------------
__global__ void topk_kernel() {
    __shared__ float sv[NPTS];
    __shared__ int   si[NPTS];
    int tid = threadIdx.x;   // 1024 threads
    int seed = g_seed;
    for (int i = tid; i < NPTS; i += 1024) { sv[i] = g_simseed[i]; si[i] = i; }
    __syncthreads();
    for (int k = 2; k <= NPTS; k <<= 1) {
        for (int j = k >> 1; j > 0; j >>= 1) {
            for (int i = tid; i < NPTS; i += 1024) {
                int ixj = i ^ j;
                if (ixj > i) {
                    float v1 = sv[i], v2 = sv[ixj];
                    int a = si[i], b = si[ixj];
                    bool g = (v1 < v2) || (v1 == v2 && a > b);
                    bool dirAsc = ((i & k) == 0);
                    if (g == dirAsc) { sv[i] = v2; sv[ixj] = v1; si[i] = b; si[ixj] = a; }
                }
            }
            __syncthreads();
        }
    }
    float v99 = sv[KTOP - 1];
    int   i99 = si[KTOP - 1];
    for (int i = tid; i < NPTS; i += 1024) {
        int s = g_s[i];
        if (i == seed) s = 1;
        float v = g_simseed[i];
        bool keep = (v > v99) || (v == v99 && i <= i99);
        g_s[i] = keep ? s : 0;
    }
}

// ---------------------------------------------------------------------------
// 5) sequential expansion, single warp, register-resident accumulator.
//    v = sum of kept features; for each kept i asc: if out[i].v <= 0 -> drop.
// ---------------------------------------------------------------------------
__global__ void scan_kernel(const float* __restrict__ X) {
    __shared__ int list[KTOP + 32];
    int lane = threadIdx.x;   // 32 threads

    // warp-parallel compaction of set indices (<= 100 after topk)
    int cnt = 0;
    for (int c = 0; c < NPTS / 32; c++) {
        int idx = c * 32 + lane;
        int val = g_s[idx];
        unsigned m = __ballot_sync(0xffffffffu, val != 0);
        if (val) {
            int pos = cnt + __popc(m & ((1u << lane) - 1));
            if (pos < KTOP + 32) list[pos] = idx;
        }
        cnt += __popc(m);
    }
    int na = (cnt < KTOP + 32) ? cnt : (KTOP + 32);
    __syncwarp();

    // v in registers: dim d = lane + 32*q
    float v[DIM / 32];
    #pragma unroll
    for (int q = 0; q < DIM / 32; q++) v[q] = 0.0f;
    for (int l = 0; l < na; l++) {
        const float* x = X + (size_t)list[l] * DIM;
        #pragma unroll
        for (int q = 0; q < DIM / 32; q++) v[q] += x[lane + 32 * q];
    }

    for (int l = 0; l < na; l++) {
        int i = list[l];
        const float* x = X + (size_t)i * DIM;
        float xr[DIM / 32];
        float dot = 0.0f;
        #pragma unroll
        for (int q = 0; q < DIM / 32; q++) {
            xr[q] = x[lane + 32 * q];
            dot += xr[q] * v[q];
        }
        #pragma unroll
        for (int o = 16; o > 0; o >>= 1) dot += __shfl_xor_sync(0xffffffffu, dot, o);
        if (dot <= 0.0f) {                 // grows = (sum > 0) fails -> drop
            if (lane == 0) g_s[i] = 0;
            #pragma unroll
            for (int q = 0; q < DIM / 32; q++) v[q] -= xr[q];
        }
    }
}

// ---------------------------------------------------------------------------
// 6) 8-connected components: in-place min-label propagation to fixpoint.
//    Output written as FLOAT (harness canonical dtype).
// ---------------------------------------------------------------------------
__global__ void cc_kernel(float* __restrict__ outp) {
    __shared__ int lab[66 * 66];
    __shared__ int changed;
    const int BIG = NPTS + 1;
    int tid = threadIdx.x;   // 1024 threads

    for (int p = tid; p < 66 * 66; p += 1024) lab[p] = BIG;
    __syncthreads();

    int fgp[4], pos[4];
    #pragma unroll
    for (int q = 0; q < 4; q++) {
        int p = tid + q * 1024;
        int r = p >> 6, c = p & 63;
        pos[q] = (r + 1) * 66 + (c + 1);
        fgp[q] = g_s[p];
        lab[pos[q]] = fgp[q] ? (p + 1) : BIG;
    }
    __syncthreads();

    while (true) {
        if (tid == 0) changed = 0;
        __syncthreads();
        int lc = 0;
        #pragma unroll
        for (int q = 0; q < 4; q++) {
            if (fgp[q]) {
                int pp = pos[q];
                int m = lab[pp];
                m = min(m, lab[pp - 67]); m = min(m, lab[pp - 66]); m = min(m, lab[pp - 65]);
                m = min(m, lab[pp - 1]);                            m = min(m, lab[pp + 1]);
                m = min(m, lab[pp + 65]); m = min(m, lab[pp + 66]); m = min(m, lab[pp + 67]);
                if (m < lab[pp]) { lab[pp] = m; lc = 1; }
            }
        }
        if (lc) changed = 1;
        __syncthreads();
        int done = !changed;
        __syncthreads();
        if (done) break;
    }

    #pragma unroll
    for (int q = 0; q < 4; q++) {
        int p = tid + q * 1024;
        outp[p] = fgp[q] ? (float)lab[pos[q]] : 0.0f;
    }
}

// ---------------------------------------------------------------------------
extern "C" void kernel_launch(void* const* d_in, const int* in_sizes, int n_in,
                              void* d_out, int out_size) {
    const float* X;
    const int*   attn;
    if (n_in >= 2 && in_sizes[0] == 2) {
        attn = (const int*)d_in[0];
        X    = (const float*)d_in[1];
    } else {
        X    = (const float*)d_in[0];
        attn = (const int*)d_in[1];
    }
    float* outp = (float*)d_out;

    convert_bf16<<<(NPTS * DIM / 4) / 256, 256>>>(X);
    init_counts<<<16, 256>>>();
    count_mma<<<dim3(32, 32), 256>>>(X);
    seed_kernel<<<1, 256>>>(attn);
    seedrow_kernel<<<NPTS / 8, 256>>>(X);
    topk_kernel<<<1, 1024>>>();
    scan_kernel<<<1, 32>>>(X);
    cc_kernel<<<1, 1024>>>(outp);
}

// round 8
// speedup vs baseline: 3.2571x; 3.2571x over previous
#include <cuda_runtime.h>
#include <cuda_bf16.h>
#include <cstdint>
#include <limits.h>

#define NPTS 4096
#define DIM  768
#define WD   64
#define KTOP 100

#define BM   128
#define NKT  (DIM / 16)     // 48 k-steps of 16
#define PADK 24             // smem row stride in bf16 (48B -> conflict-free LDSM)
#define TAU  0.05f          // |acc| below this -> exact fp32 sign repair (~250 sigma)

// scratch (no allocations allowed)
__device__ int            g_counts[NPTS];
__device__ int            g_seed;
__device__ float          g_simseed[NPTS];
__device__ int            g_s[NPTS];
__device__ __nv_bfloat16  g_Xh[NPTS * DIM];     // bf16 hi part (6.3MB)
__device__ __nv_bfloat16  g_Xl[NPTS * DIM];     // bf16 lo part (6.3MB)

// ---------------------------------------------------------------------------
// helpers: ldmatrix + mma
// ---------------------------------------------------------------------------
__device__ __forceinline__ void ldsm_x4(uint32_t r[4], uint32_t addr) {
    asm volatile("ldmatrix.sync.aligned.m8n8.x4.shared.b16 {%0,%1,%2,%3}, [%4];"
                 : "=r"(r[0]), "=r"(r[1]), "=r"(r[2]), "=r"(r[3]) : "r"(addr));
}
__device__ __forceinline__ void mma_bf16(float d[4], const uint32_t a[4],
                                         uint32_t b0, uint32_t b1) {
    asm volatile("mma.sync.aligned.m16n8k16.row.col.f32.bf16.bf16.f32 "
                 "{%0,%1,%2,%3},{%4,%5,%6,%7},{%8,%9},{%0,%1,%2,%3};"
                 : "+f"(d[0]), "+f"(d[1]), "+f"(d[2]), "+f"(d[3])
                 : "r"(a[0]), "r"(a[1]), "r"(a[2]), "r"(a[3]), "r"(b0), "r"(b1));
}

__device__ __forceinline__ float exact_dot(const float* __restrict__ X, int gi, int gj) {
    const float4* a = (const float4*)(X + (size_t)gi * DIM);
    const float4* b = (const float4*)(X + (size_t)gj * DIM);
    float s = 0.0f;
    #pragma unroll 4
    for (int d = 0; d < DIM / 4; d++) {
        float4 u = a[d], w = b[d];
        s += u.x * w.x + u.y * w.y + u.z * w.z + u.w * w.w;
    }
    return s;
}

// ---------------------------------------------------------------------------
// 0a) fp32 -> (bf16 hi, bf16 lo) split: x ~= hi + lo to ~16 mantissa bits
// ---------------------------------------------------------------------------
__global__ void convert_split(const float* __restrict__ X) {
    int i = blockIdx.x * blockDim.x + threadIdx.x;   // one float4 per thread
    float4 v = ((const float4*)X)[i];
    __nv_bfloat16 hx = __float2bfloat16_rn(v.x);
    __nv_bfloat16 hy = __float2bfloat16_rn(v.y);
    __nv_bfloat16 hz = __float2bfloat16_rn(v.z);
    __nv_bfloat16 hw = __float2bfloat16_rn(v.w);
    float lx = v.x - __bfloat162float(hx);
    float ly = v.y - __bfloat162float(hy);
    float lz = v.z - __bfloat162float(hz);
    float lw = v.w - __bfloat162float(hw);
    __nv_bfloat162* oh = (__nv_bfloat162*)g_Xh;
    __nv_bfloat162* ol = (__nv_bfloat162*)g_Xl;
    oh[2 * i + 0] = __nv_bfloat162(hx, hy);
    oh[2 * i + 1] = __nv_bfloat162(hz, hw);
    ol[2 * i + 0] = __floats2bfloat162_rn(lx, ly);
    ol[2 * i + 1] = __floats2bfloat162_rn(lz, lw);
}

// ---------------------------------------------------------------------------
// 0b) init counts to 1 (diagonal sim[i][i] >= 0 always)
// ---------------------------------------------------------------------------
__global__ void init_counts() {
    int i = blockIdx.x * blockDim.x + threadIdx.x;
    if (i < NPTS) g_counts[i] = 1;
}

// ---------------------------------------------------------------------------
// 1) triangular count-GEMM on tensor cores: 3-pass bf16 (hh + hl + lh) into
//    one fp32 accumulator; residual error ~2e-4 -> repairs are ~0.06%.
//    128x128 tile, 8 warps (4x2), warp tile 32x64, m16n8k16.
// ---------------------------------------------------------------------------
__global__ __launch_bounds__(256)
void count_mma(const float* __restrict__ X) {
    int bi = blockIdx.y, bj = blockIdx.x;
    if (bj < bi) return;

    __shared__ __nv_bfloat16 Ah[BM * PADK], Al[BM * PADK];
    __shared__ __nv_bfloat16 Bh[BM * PADK], Bl[BM * PADK];
    __shared__ int rowSum[BM];
    __shared__ int colSum[BM];

    int tid  = threadIdx.x;
    int warp = tid >> 5, lane = tid & 31;
    int wm = warp & 3;          // M group: rows wm*32..+31
    int wn = warp >> 2;         // N group: cols wn*64..+63
    int i0 = bi * BM, j0 = bj * BM;

    float acc[2][8][4];
    #pragma unroll
    for (int im = 0; im < 2; im++)
        #pragma unroll
        for (int jn = 0; jn < 8; jn++)
            #pragma unroll
            for (int e = 0; e < 4; e++) acc[im][jn][e] = 0.0f;

    // global load mapping: thread -> (row, 16B half) of the 128x16 stage
    int lrow = tid >> 1, lhalf = tid & 1;
    const uint4* gah = (const uint4*)(g_Xh + (size_t)(i0 + lrow) * DIM);
    const uint4* gal = (const uint4*)(g_Xl + (size_t)(i0 + lrow) * DIM);
    const uint4* gbh = (const uint4*)(g_Xh + (size_t)(j0 + lrow) * DIM);
    const uint4* gbl = (const uint4*)(g_Xl + (size_t)(j0 + lrow) * DIM);
    uint4* sah = (uint4*)(&Ah[lrow * PADK + lhalf * 8]);
    uint4* sal = (uint4*)(&Al[lrow * PADK + lhalf * 8]);
    uint4* sbh = (uint4*)(&Bh[lrow * PADK + lhalf * 8]);
    uint4* sbl = (uint4*)(&Bl[lrow * PADK + lhalf * 8]);

    // ldmatrix source lanes
    int rowA  = lane & 15;
    int koffA = (lane >> 4) * 8;
    int grp   = lane >> 3;
    int nB    = ((grp >> 1) * 8) + (lane & 7);
    int koffB = (grp & 1) * 8;

    uint32_t aAddrH[2], aAddrL[2], bAddrH[4], bAddrL[4];
    {
        uint32_t abh = (uint32_t)__cvta_generic_to_shared(&Ah[0]);
        uint32_t abl = (uint32_t)__cvta_generic_to_shared(&Al[0]);
        uint32_t bbh = (uint32_t)__cvta_generic_to_shared(&Bh[0]);
        uint32_t bbl = (uint32_t)__cvta_generic_to_shared(&Bl[0]);
        #pragma unroll
        for (int im = 0; im < 2; im++) {
            uint32_t off = ((wm * 32 + im * 16 + rowA) * PADK + koffA) * 2;
            aAddrH[im] = abh + off;  aAddrL[im] = abl + off;
        }
        #pragma unroll
        for (int jb = 0; jb < 4; jb++) {
            uint32_t off = ((wn * 64 + jb * 16 + nB) * PADK + koffB) * 2;
            bAddrH[jb] = bbh + off;  bAddrL[jb] = bbl + off;
        }
    }

    uint4 rah, ral, rbh, rbl;
    rah = gah[lhalf]; ral = gal[lhalf]; rbh = gbh[lhalf]; rbl = gbl[lhalf];
    *sah = rah; *sal = ral; *sbh = rbh; *sbl = rbl;
    __syncthreads();

    for (int kt = 0; kt < NKT; kt++) {
        if (kt + 1 < NKT) {          // prefetch next stage into registers
            int o = (kt + 1) * 2 + lhalf;
            rah = gah[o]; ral = gal[o]; rbh = gbh[o]; rbl = gbl[o];
        }

        uint32_t ah[2][4], al[2][4], bh[4][4], bl[4][4];
        #pragma unroll
        for (int im = 0; im < 2; im++) { ldsm_x4(ah[im], aAddrH[im]); ldsm_x4(al[im], aAddrL[im]); }
        #pragma unroll
        for (int jb = 0; jb < 4; jb++) { ldsm_x4(bh[jb], bAddrH[jb]); ldsm_x4(bl[jb], bAddrL[jb]); }

        __syncthreads();             // all smem reads complete
        if (kt + 1 < NKT) { *sah = rah; *sal = ral; *sbh = rbh; *sbl = rbl; }

        #pragma unroll
        for (int im = 0; im < 2; im++)
            #pragma unroll
            for (int jn = 0; jn < 8; jn++) {
                int jb = jn >> 1, o = (jn & 1) * 2;
                mma_bf16(acc[im][jn], ah[im], bh[jb][o], bh[jb][o + 1]);
                mma_bf16(acc[im][jn], ah[im], bl[jb][o], bl[jb][o + 1]);
                mma_bf16(acc[im][jn], al[im], bh[jb][o], bh[jb][o + 1]);
            }

        __syncthreads();             // stores visible before next ldsm
    }

    // ---- epilogue: signs (+ rare exact repair), row/col counts ----
    if (tid < BM) { rowSum[tid] = 0; colSum[tid] = 0; }
    __syncthreads();

    bool diag = (bi == bj);
    int rcnt[2][2];  rcnt[0][0] = rcnt[0][1] = rcnt[1][0] = rcnt[1][1] = 0;
    int ccnt[16];
    #pragma unroll
    for (int q = 0; q < 16; q++) ccnt[q] = 0;

    int rbase = wm * 32 + (lane >> 2);
    int cbase = wn * 64 + (lane & 3) * 2;

    #pragma unroll
    for (int im = 0; im < 2; im++) {
        #pragma unroll
        for (int jn = 0; jn < 8; jn++) {
            #pragma unroll
            for (int e4 = 0; e4 < 4; e4++) {
                int h = e4 >> 1, e = e4 & 1;
                int gi = i0 + rbase + im * 16 + h * 8;
                int gj = j0 + cbase + jn * 8 + e;
                if (diag && gj <= gi) continue;
                float v = acc[im][jn][e4];
                int c;
                if (fabsf(v) >= TAU) c = (v >= 0.0f);
                else                 c = (exact_dot(X, gi, gj) >= 0.0f);
                rcnt[im][h] += c;
                ccnt[jn * 2 + e] += c;
            }
        }
    }
    #pragma unroll
    for (int im = 0; im < 2; im++)
        #pragma unroll
        for (int h = 0; h < 2; h++)
            atomicAdd(&rowSum[rbase + im * 16 + h * 8], rcnt[im][h]);
    #pragma unroll
    for (int jn = 0; jn < 8; jn++)
        #pragma unroll
        for (int e = 0; e < 2; e++)
            atomicAdd(&colSum[cbase + jn * 8 + e], ccnt[jn * 2 + e]);
    __syncthreads();

    if (tid < BM) {
        if (rowSum[tid]) atomicAdd(&g_counts[i0 + tid], rowSum[tid]);
        if (colSum[tid]) atomicAdd(&g_counts[j0 + tid], colSum[tid]);
    }
}

// ---------------------------------------------------------------------------
// 2) argmin of counts (first occurrence) + seed blend w/ round-half-to-even
// ---------------------------------------------------------------------------
__global__ void seed_kernel(const int* __restrict__ attn_seed) {
    __shared__ int bestC[256], bestI[256];
    int tid = threadIdx.x;
    int bc = INT_MAX, bi = 0;
    for (int i = tid; i < NPTS; i += 256) {
        int c = g_counts[i];
        if (c < bc) { bc = c; bi = i; }
    }
    bestC[tid] = bc; bestI[tid] = bi;
    __syncthreads();
    for (int s = 128; s > 0; s >>= 1) {
        if (tid < s) {
            if (bestC[tid + s] < bestC[tid] ||
                (bestC[tid + s] == bestC[tid] && bestI[tid + s] < bestI[tid])) {
                bestC[tid] = bestC[tid + s];
                bestI[tid] = bestI[tid + s];
            }
        }
        __syncthreads();
    }
    if (tid == 0) {
        int idx = bestI[0];
        int r = idx / WD, c = idx % WD;
        int tr = r + attn_seed[0];
        int tc = c + attn_seed[1];
        int rr = tr >> 1; if (tr & 1) rr += (rr & 1);   // round half-to-even
        int cc = tc >> 1; if (tc & 1) cc += (cc & 1);
        g_seed = rr * WD + cc;
    }
}

// ---------------------------------------------------------------------------
// 3) sim[seed][j] for all j + initial mask s[j] = (sim >= 0). warp per j.
// ---------------------------------------------------------------------------
__global__ void seedrow_kernel(const float* __restrict__ X) {
    int gwarp = (blockIdx.x * blockDim.x + threadIdx.x) >> 5;
    int lane  = threadIdx.x & 31;
    if (gwarp >= NPTS) return;
    int seed = g_seed;
    const float* xs = X + (size_t)seed * DIM;
    const float* xj = X + (size_t)gwarp * DIM;
    float p = 0.0f;
    for (int d = lane; d < DIM; d += 32) p += xs[d] * xj[d];
    #pragma unroll
    for (int o = 16; o > 0; o >>= 1) p += __shfl_down_sync(0xffffffffu, p, o);
    if (lane == 0) {
        g_simseed[gwarp] = p;
        g_s[gwarp] = (p >= 0.0f) ? 1 : 0;
    }
}

// ---------------------------------------------------------------------------
// 4) bitonic sort (desc value, asc index tiebreak) -> keep top-100, mask s
// ---------------------------------------------------------------------------
__global__ void topk_kernel() {
    __shared__ float sv[NPTS];
    __shared__ int   si[NPTS];
    int tid = threadIdx.x;   // 1024 threads
    int seed = g_seed;
    for (int i = tid; i < NPTS; i += 1024) { sv[i] = g_simseed[i]; si[i] = i; }
    __syncthreads();
    for (int k = 2; k <= NPTS; k <<= 1) {
        for (int j = k >> 1; j > 0; j >>= 1) {
            for (int i = tid; i < NPTS; i += 1024) {
                int ixj = i ^ j;
                if (ixj > i) {
                    float v1 = sv[i], v2 = sv[ixj];
                    int a = si[i], b = si[ixj];
                    bool g = (v1 < v2) || (v1 == v2 && a > b);
                    bool dirAsc = ((i & k) == 0);
                    if (g == dirAsc) { sv[i] = v2; sv[ixj] = v1; si[i] = b; si[ixj] = a; }
                }
            }
            __syncthreads();
        }
    }
    float v99 = sv[KTOP - 1];
    int   i99 = si[KTOP - 1];
    for (int i = tid; i < NPTS; i += 1024) {
        int s = g_s[i];
        if (i == seed) s = 1;
        float v = g_simseed[i];
        bool keep = (v > v99) || (v == v99 && i <= i99);
        g_s[i] = keep ? s : 0;
    }
}

// ---------------------------------------------------------------------------
// 5) sequential expansion, single warp, register-resident accumulator.
// ---------------------------------------------------------------------------
__global__ void scan_kernel(const float* __restrict__ X) {
    __shared__ int list[KTOP + 32];
    int lane = threadIdx.x;   // 32 threads

    int cnt = 0;
    for (int c = 0; c < NPTS / 32; c++) {
        int idx = c * 32 + lane;
        int val = g_s[idx];
        unsigned m = __ballot_sync(0xffffffffu, val != 0);
        if (val) {
            int pos = cnt + __popc(m & ((1u << lane) - 1));
            if (pos < KTOP + 32) list[pos] = idx;
        }
        cnt += __popc(m);
    }
    int na = (cnt < KTOP + 32) ? cnt : (KTOP + 32);
    __syncwarp();

    float v[DIM / 32];
    #pragma unroll
    for (int q = 0; q < DIM / 32; q++) v[q] = 0.0f;
    for (int l = 0; l < na; l++) {
        const float* x = X + (size_t)list[l] * DIM;
        #pragma unroll
        for (int q = 0; q < DIM / 32; q++) v[q] += x[lane + 32 * q];
    }

    for (int l = 0; l < na; l++) {
        int i = list[l];
        const float* x = X + (size_t)i * DIM;
        float xr[DIM / 32];
        float dot = 0.0f;
        #pragma unroll
        for (int q = 0; q < DIM / 32; q++) {
            xr[q] = x[lane + 32 * q];
            dot += xr[q] * v[q];
        }
        #pragma unroll
        for (int o = 16; o > 0; o >>= 1) dot += __shfl_xor_sync(0xffffffffu, dot, o);
        if (dot <= 0.0f) {
            if (lane == 0) g_s[i] = 0;
            #pragma unroll
            for (int q = 0; q < DIM / 32; q++) v[q] -= xr[q];
        }
    }
}

// ---------------------------------------------------------------------------
// 6) 8-connected components: in-place min-label propagation to fixpoint.
// ---------------------------------------------------------------------------
__global__ void cc_kernel(float* __restrict__ outp) {
    __shared__ int lab[66 * 66];
    __shared__ int changed;
    const int BIG = NPTS + 1;
    int tid = threadIdx.x;   // 1024 threads

    for (int p = tid; p < 66 * 66; p += 1024) lab[p] = BIG;
    __syncthreads();

    int fgp[4], pos[4];
    #pragma unroll
    for (int q = 0; q < 4; q++) {
        int p = tid + q * 1024;
        int r = p >> 6, c = p & 63;
        pos[q] = (r + 1) * 66 + (c + 1);
        fgp[q] = g_s[p];
        lab[pos[q]] = fgp[q] ? (p + 1) : BIG;
    }
    __syncthreads();

    while (true) {
        if (tid == 0) changed = 0;
        __syncthreads();
        int lc = 0;
        #pragma unroll
        for (int q = 0; q < 4; q++) {
            if (fgp[q]) {
                int pp = pos[q];
                int m = lab[pp];
                m = min(m, lab[pp - 67]); m = min(m, lab[pp - 66]); m = min(m, lab[pp - 65]);
                m = min(m, lab[pp - 1]);                            m = min(m, lab[pp + 1]);
                m = min(m, lab[pp + 65]); m = min(m, lab[pp + 66]); m = min(m, lab[pp + 67]);
                if (m < lab[pp]) { lab[pp] = m; lc = 1; }
            }
        }
        if (lc) changed = 1;
        __syncthreads();
        int done = !changed;
        __syncthreads();
        if (done) break;
    }

    #pragma unroll
    for (int q = 0; q < 4; q++) {
        int p = tid + q * 1024;
        outp[p] = fgp[q] ? (float)lab[pos[q]] : 0.0f;
    }
}

// ---------------------------------------------------------------------------
extern "C" void kernel_launch(void* const* d_in, const int* in_sizes, int n_in,
                              void* d_out, int out_size) {
    const float* X;
    const int*   attn;
    if (n_in >= 2 && in_sizes[0] == 2) {
        attn = (const int*)d_in[0];
        X    = (const float*)d_in[1];
    } else {
        X    = (const float*)d_in[0];
        attn = (const int*)d_in[1];
    }
    float* outp = (float*)d_out;

    convert_split<<<(NPTS * DIM / 4) / 256, 256>>>(X);
    init_counts<<<16, 256>>>();
    count_mma<<<dim3(32, 32), 256>>>(X);
    seed_kernel<<<1, 256>>>(attn);
    seedrow_kernel<<<NPTS / 8, 256>>>(X);
    topk_kernel<<<1, 1024>>>();
    scan_kernel<<<1, 32>>>(X);
    cc_kernel<<<1, 1024>>>(outp);
}